// round 13
// baseline (speedup 1.0000x reference)
#include <cuda_runtime.h>
#include <cuda_bf16.h>

// Problem constants (fixed by the reference).
#define N_  512
#define L_  5
#define H_  8
#define D_  16
#define E_  10000

// Scratch: projected edge table P[e][l][h] = dot(edge_features[e], W[1+l][h]).
// E*L*H = 400,000 floats = 1.6 MB (L2-resident). Row stride per e = 40 floats
// = 160 B. Chunk (e,l) = 32 B at offset e*160 + l*32; since 160 ≡ 32 (mod 128),
// every chunk is 32B-aligned inside a single 128B line (never straddles).
__device__ float g_P[E_ * L_ * H_];

// ---------------------------------------------------------------------------
// Kernel 1 (PDL primary): projection, R7 form (empirically fastest).
// One thread per edge e computes all 40 (l,h) dots. W rows 1..L in smem.
// ---------------------------------------------------------------------------
__global__ void __launch_bounds__(128)
project_kernel(const float* __restrict__ F,   // [E, D]
               const float* __restrict__ W)   // [L+1, H*D]
{
    __shared__ float sW[L_ * H_ * D_];        // 640 floats, rows 1..L
    for (int i = threadIdx.x; i < L_ * H_ * D_; i += blockDim.x)
        sW[i] = W[H_ * D_ + i];               // skip row 0
    __syncthreads();

    int e = blockIdx.x * blockDim.x + threadIdx.x;
    if (e >= E_) return;

    const float4* fp = reinterpret_cast<const float4*>(F + (size_t)e * D_);
    float4 f0 = fp[0], f1 = fp[1], f2 = fp[2], f3 = fp[3];
    float fr[D_] = { f0.x, f0.y, f0.z, f0.w,
                     f1.x, f1.y, f1.z, f1.w,
                     f2.x, f2.y, f2.z, f2.w,
                     f3.x, f3.y, f3.z, f3.w };

    float out[L_ * H_];
    #pragma unroll
    for (int l = 0; l < L_; ++l) {
        #pragma unroll
        for (int h = 0; h < H_; ++h) {
            float acc = 0.0f;
            const float* w = &sW[(l * H_ + h) * D_];
            #pragma unroll
            for (int d = 0; d < D_; ++d)
                acc = fmaf(fr[d], w[d], acc);
            out[l * H_ + h] = acc;
        }
    }

    float4* dst = reinterpret_cast<float4*>(g_P + (size_t)e * (L_ * H_));
    #pragma unroll
    for (int i = 0; i < (L_ * H_) / 4; ++i) {
        float4 v = { out[4*i], out[4*i+1], out[4*i+2], out[4*i+3] };
        dst[i] = v;
    }
}

// ---------------------------------------------------------------------------
// Kernel 2 (PDL secondary): gather/average, R10-best shape.
// 256 threads / 256 pairs per block (grid 1024). Thread-pair (2 lanes) per
// output pair: lane c loads float4 chunk c of the 32B P-row chunk -> both
// lanes hit the SAME 128B line (one L1 wavefront per gather). PP=2 pairs per
// thread (10 independent LDG.128 in flight).
//
// PDL: this kernel launches while project_kernel is still running. The index
// loads (independent of g_P) are issued FIRST, then
// cudaGridDependencySynchronize() waits for project completion before any
// g_P access. Index DRAM latency + project runtime overlap fully.
//
// Branchless: invalid index (-1) loads row 0 (hot line), mask-accumulated.
// Divisor = max(valid_count, 1). Indices arrive as int32.
// ---------------------------------------------------------------------------
#define PAIRS_PER_BLK 256
#define THREADS_G     256
#define PP_           2

__global__ void __launch_bounds__(THREADS_G)
gather_kernel(const int* __restrict__ spe,   // [N, N, L] int32
              float* __restrict__ out)       // [H, N, N]
{
    __shared__ float s_out[H_ * (PAIRS_PER_BLK + 1)];  // padded stride

    const int base = blockIdx.x * PAIRS_PER_BLK;
    const int tid  = threadIdx.x;
    const int pair = tid >> 1;      // 0..127
    const int c    = tid & 1;       // float4 chunk within the 32B row chunk
    const int coff = c * 4;

    // Issue ALL index loads before the PDL dependency sync: they read only
    // the input buffer, never g_P, so they fly while project still runs.
    // Both lanes of a pair load identical addresses (same-line broadcast).
    int idx[PP_][L_];
    #pragma unroll
    for (int pp = 0; pp < PP_; ++pp) {
        const int pr = base + pair + pp * 128;
        const int* p = spe + (size_t)pr * L_;
        #pragma unroll
        for (int l = 0; l < L_; ++l)
            idx[pp][l] = __ldg(p + l);
    }

    // Wait for project_kernel's g_P writes to be visible.
    cudaGridDependencySynchronize();

    float a[PP_][4];
    float cntf[PP_];
    #pragma unroll
    for (int pp = 0; pp < PP_; ++pp) {
        a[pp][0] = a[pp][1] = a[pp][2] = a[pp][3] = 0.f;
        cntf[pp] = 0.f;
    }

    #pragma unroll
    for (int pp = 0; pp < PP_; ++pp) {
        #pragma unroll
        for (int l = 0; l < L_; ++l) {
            int e = idx[pp][l];
            bool valid = (unsigned)e < (unsigned)E_;
            int  ei    = valid ? e : 0;
            float m    = valid ? 1.0f : 0.0f;
            const float4 v = *reinterpret_cast<const float4*>(
                g_P + (size_t)ei * (L_ * H_) + l * H_ + coff);
            a[pp][0] = fmaf(m, v.x, a[pp][0]);
            a[pp][1] = fmaf(m, v.y, a[pp][1]);
            a[pp][2] = fmaf(m, v.z, a[pp][2]);
            a[pp][3] = fmaf(m, v.w, a[pp][3]);
            cntf[pp] += m;
        }
    }

    #pragma unroll
    for (int pp = 0; pp < PP_; ++pp) {
        const int pr  = pair + pp * 128;
        float inv = 1.0f / fmaxf(cntf[pp], 1.0f);
        s_out[(coff + 0) * (PAIRS_PER_BLK + 1) + pr] = a[pp][0] * inv;
        s_out[(coff + 1) * (PAIRS_PER_BLK + 1) + pr] = a[pp][1] * inv;
        s_out[(coff + 2) * (PAIRS_PER_BLK + 1) + pr] = a[pp][2] * inv;
        s_out[(coff + 3) * (PAIRS_PER_BLK + 1) + pr] = a[pp][3] * inv;
    }
    __syncthreads();

    // 8 planes x 256 pairs, fully coalesced (1KB contiguous per plane seg).
    const int NN = N_ * N_;
    #pragma unroll
    for (int k = 0; k < (H_ * PAIRS_PER_BLK) / THREADS_G; ++k) {
        int i = k * THREADS_G + tid;
        int h = i >> 8;            // /256
        int j = i & 255;           // %256
        out[h * NN + base + j] = s_out[h * (PAIRS_PER_BLK + 1) + j];
    }
}

// ---------------------------------------------------------------------------
// Launch: inputs in metadata order:
//   d_in[0] = edge_features_s      float32 [E*D]
//   d_in[1] = edge_weights         float32 [(L+1)*H*D]
//   d_in[2] = shortest_path_edges  int32   [N*N*L]
// d_out = float32 [H*N*N]
//
// gather_kernel is launched with Programmatic Stream Serialization so it
// overlaps with project_kernel; the in-kernel
// cudaGridDependencySynchronize() enforces the g_P dependency.
// ---------------------------------------------------------------------------
extern "C" void kernel_launch(void* const* d_in, const int* in_sizes, int n_in,
                              void* d_out, int out_size)
{
    const float* F   = (const float*)d_in[0];
    const float* W   = (const float*)d_in[1];
    const int*   spe = (const int*)d_in[2];
    float*       out = (float*)d_out;

    project_kernel<<<(E_ + 127) / 128, 128>>>(F, W);

    cudaLaunchConfig_t cfg = {};
    cfg.gridDim  = dim3((N_ * N_) / PAIRS_PER_BLK, 1, 1);   // 1024
    cfg.blockDim = dim3(THREADS_G, 1, 1);
    cfg.dynamicSmemBytes = 0;
    cfg.stream = 0;
    cudaLaunchAttribute attrs[1];
    attrs[0].id = cudaLaunchAttributeProgrammaticStreamSerialization;
    attrs[0].val.programmaticStreamSerializationAllowed = 1;
    cfg.attrs = attrs;
    cfg.numAttrs = 1;
    cudaLaunchKernelEx(&cfg, gather_kernel, spe, out);
}

// round 14
// speedup vs baseline: 1.0020x; 1.0020x over previous
#include <cuda_runtime.h>
#include <cuda_bf16.h>

// Problem constants (fixed by the reference).
#define N_  512
#define L_  5
#define H_  8
#define D_  16
#define E_  10000

// Scratch: projected edge table P[e][l][h] = dot(edge_features[e], W[1+l][h]).
// E*L*H = 400,000 floats = 1.6 MB (L2-resident). Row stride per e = 40 floats
// = 160 B. Chunk (e,l) = 32 B at offset e*160 + l*32; since 160 ≡ 32 (mod 128),
// every chunk is 32B-aligned inside a single 128B line (never straddles).
__device__ float g_P[E_ * L_ * H_];

// ---------------------------------------------------------------------------
// Kernel 1: projection, R7 per-e form (empirically fastest; rest-of-total
// = 4.6-4.8 us across R11-R13 with this form vs 8.7 with per-(e,l)).
// ---------------------------------------------------------------------------
__global__ void __launch_bounds__(128)
project_kernel(const float* __restrict__ F,   // [E, D]
               const float* __restrict__ W)   // [L+1, H*D]
{
    __shared__ float sW[L_ * H_ * D_];        // 640 floats, rows 1..L
    for (int i = threadIdx.x; i < L_ * H_ * D_; i += blockDim.x)
        sW[i] = W[H_ * D_ + i];               // skip row 0
    __syncthreads();

    int e = blockIdx.x * blockDim.x + threadIdx.x;
    if (e >= E_) return;

    const float4* fp = reinterpret_cast<const float4*>(F + (size_t)e * D_);
    float4 f0 = fp[0], f1 = fp[1], f2 = fp[2], f3 = fp[3];
    float fr[D_] = { f0.x, f0.y, f0.z, f0.w,
                     f1.x, f1.y, f1.z, f1.w,
                     f2.x, f2.y, f2.z, f2.w,
                     f3.x, f3.y, f3.z, f3.w };

    float out[L_ * H_];
    #pragma unroll
    for (int l = 0; l < L_; ++l) {
        #pragma unroll
        for (int h = 0; h < H_; ++h) {
            float acc = 0.0f;
            const float* w = &sW[(l * H_ + h) * D_];
            #pragma unroll
            for (int d = 0; d < D_; ++d)
                acc = fmaf(fr[d], w[d], acc);
            out[l * H_ + h] = acc;
        }
    }

    float4* dst = reinterpret_cast<float4*>(g_P + (size_t)e * (L_ * H_));
    #pragma unroll
    for (int i = 0; i < (L_ * H_) / 4; ++i) {
        float4 v = { out[4*i], out[4*i+1], out[4*i+2], out[4*i+3] };
        dst[i] = v;
    }
}

// ---------------------------------------------------------------------------
// Kernel 2: gather/average — EXACT R10 shape (measured best: 10.8 us).
// 256 threads / 256 pairs per block, grid 1024. Thread-pair (2 lanes) per
// output pair: lane c loads float4 chunk c of the 32B P-row chunk -> both
// lanes hit the SAME 128B line (one L1 wavefront per gather). PP=2 pairs
// per thread (10 independent gathers in flight). Index staging through smem
// as int4 (coalesced; R13 showed direct per-thread idx loads cost ~1 us of
// extra wavefronts).
//
// EXPERIMENT (single variable vs R10): P loads use ld.global.cg (L2-only).
// Tests whether the within-LDG divergent replay floor (2.07 cyc/line) is an
// L1-fill artifact; P's L1 hit rate is <=14% so the lost caching is cheap.
//
// Branchless: invalid index (-1) loads row 0 (hot line), mask-accumulated.
// Divisor = max(valid_count, 1). Indices arrive as int32.
// ---------------------------------------------------------------------------
#define PAIRS_PER_BLK 256
#define THREADS_G     256
#define PP_           2

__device__ __forceinline__ float4 ldg_cg_f4(const float* p) {
    float4 v;
    asm volatile("ld.global.cg.v4.f32 {%0, %1, %2, %3}, [%4];"
                 : "=f"(v.x), "=f"(v.y), "=f"(v.z), "=f"(v.w)
                 : "l"(p));
    return v;
}

__global__ void __launch_bounds__(THREADS_G)
gather_kernel(const int* __restrict__ spe,   // [N, N, L] int32
              float* __restrict__ out)       // [H, N, N]
{
    __shared__ int   s_idx[PAIRS_PER_BLK * L_];        // 1280 ints
    __shared__ float s_out[H_ * (PAIRS_PER_BLK + 1)];  // padded stride

    const int base = blockIdx.x * PAIRS_PER_BLK;
    const int tid  = threadIdx.x;

    // Coalesced index staging: 1280 ints = 320 int4 (base*5*4 = blk*5120 B,
    // 16B-aligned).
    const int4* g4 = reinterpret_cast<const int4*>(spe + (size_t)base * L_);
    #pragma unroll
    for (int i = tid; i < (PAIRS_PER_BLK * L_) / 4; i += THREADS_G)
        reinterpret_cast<int4*>(s_idx)[i] = g4[i];
    __syncthreads();

    const int pair = tid >> 1;      // 0..127
    const int c    = tid & 1;       // float4 chunk within the 32B row chunk
    const int coff = c * 4;

    float a[PP_][4];
    float cntf[PP_];
    #pragma unroll
    for (int pp = 0; pp < PP_; ++pp) {
        a[pp][0] = a[pp][1] = a[pp][2] = a[pp][3] = 0.f;
        cntf[pp] = 0.f;
    }

    #pragma unroll
    for (int pp = 0; pp < PP_; ++pp) {
        const int pr = pair + pp * 128;
        #pragma unroll
        for (int l = 0; l < L_; ++l) {
            int e = s_idx[pr * L_ + l];
            bool valid = (unsigned)e < (unsigned)E_;
            int  ei    = valid ? e : 0;
            float m    = valid ? 1.0f : 0.0f;
            float4 v = ldg_cg_f4(g_P + (size_t)ei * (L_ * H_) + l * H_ + coff);
            a[pp][0] = fmaf(m, v.x, a[pp][0]);
            a[pp][1] = fmaf(m, v.y, a[pp][1]);
            a[pp][2] = fmaf(m, v.z, a[pp][2]);
            a[pp][3] = fmaf(m, v.w, a[pp][3]);
            cntf[pp] += m;
        }
    }

    #pragma unroll
    for (int pp = 0; pp < PP_; ++pp) {
        const int pr  = pair + pp * 128;
        float inv = 1.0f / fmaxf(cntf[pp], 1.0f);
        s_out[(coff + 0) * (PAIRS_PER_BLK + 1) + pr] = a[pp][0] * inv;
        s_out[(coff + 1) * (PAIRS_PER_BLK + 1) + pr] = a[pp][1] * inv;
        s_out[(coff + 2) * (PAIRS_PER_BLK + 1) + pr] = a[pp][2] * inv;
        s_out[(coff + 3) * (PAIRS_PER_BLK + 1) + pr] = a[pp][3] * inv;
    }
    __syncthreads();

    // 8 planes x 256 pairs, fully coalesced (1KB contiguous per plane seg).
    const int NN = N_ * N_;
    #pragma unroll
    for (int k = 0; k < (H_ * PAIRS_PER_BLK) / THREADS_G; ++k) {
        int i = k * THREADS_G + tid;
        int h = i >> 8;            // /256
        int j = i & 255;           // %256
        out[h * NN + base + j] = s_out[h * (PAIRS_PER_BLK + 1) + j];
    }
}

// ---------------------------------------------------------------------------
// Launch: inputs in metadata order:
//   d_in[0] = edge_features_s      float32 [E*D]
//   d_in[1] = edge_weights         float32 [(L+1)*H*D]
//   d_in[2] = shortest_path_edges  int32   [N*N*L]
// d_out = float32 [H*N*N]
// ---------------------------------------------------------------------------
extern "C" void kernel_launch(void* const* d_in, const int* in_sizes, int n_in,
                              void* d_out, int out_size)
{
    const float* F   = (const float*)d_in[0];
    const float* W   = (const float*)d_in[1];
    const int*   spe = (const int*)d_in[2];
    float*       out = (float*)d_out;

    project_kernel<<<(E_ + 127) / 128, 128>>>(F, W);
    gather_kernel<<<(N_ * N_) / PAIRS_PER_BLK, THREADS_G>>>(spe, out);
}